// round 2
// baseline (speedup 1.0000x reference)
#include <cuda_runtime.h>
#include <math.h>

#define PI_F 3.14159265358979323846f

// Problem constants (from reference setup_inputs)
#define BB 8
#define HH 512
#define WW 1024

// ---------- static scratch (no runtime allocation allowed) ----------
// ref downsampled planar levels 1..3 : 8*3*(256*512 + 128*256 + 64*128)
__device__ float g_refds[4128768];
// tgt interleaved (B,h,w,3) levels 0..3 per image
// L0: 12,582,912  L1: 3,145,728  L2: 786,432  L3: 196,608  => 16,711,680
__device__ float g_tgtI0[16711680];
__device__ float g_tgtI1[16711680];
__device__ float g_R[BB * 2 * 9];
__device__ float g_t[BB * 2 * 3];
__device__ double g_acc[4];

// ---------- pose -> R,t + zero accumulators ----------
__global__ void bp_pose_init(const float* __restrict__ pose) {
    int i = threadIdx.x;
    if (i < 4) g_acc[i] = 0.0;
    if (i < BB * 2) {
        const float* p = pose + i * 6;
        float rx = p[3], ry = p[4], rz = p[5];
        float th = sqrtf(rx * rx + ry * ry + rz * rz);
        float inv = 1.0f / fmaxf(th, 1e-8f);
        float kx = rx * inv, ky = ry * inv, kz = rz * inv;
        float s = sinf(th), c = cosf(th), ic = 1.0f - c;
        float* R = g_R + i * 9;
        R[0] = c + ic * kx * kx;      R[1] = ic * kx * ky - s * kz; R[2] = ic * kx * kz + s * ky;
        R[3] = ic * ky * kx + s * kz; R[4] = c + ic * ky * ky;      R[5] = ic * ky * kz - s * kx;
        R[6] = ic * kz * kx - s * ky; R[7] = ic * kz * ky + s * kx; R[8] = c + ic * kz * kz;
        float* t = g_t + i * 3;
        t[0] = p[0]; t[1] = p[1]; t[2] = p[2];
    }
}

// ---------- planar (B,3,h,w) -> interleaved (B,h,w,3) ----------
__global__ void bp_transpose(const float* __restrict__ src, float* __restrict__ dst, int hw) {
    int idx = blockIdx.x * blockDim.x + threadIdx.x;
    int total = BB * hw;
    if (idx >= total) return;
    int b = idx / hw, p = idx - b * hw;
    const float* s = src + (size_t)b * 3 * hw + p;
    float v0 = s[0], v1 = s[hw], v2 = s[2 * hw];
    float* d = dst + (size_t)idx * 3;
    d[0] = v0; d[1] = v1; d[2] = v2;
}

// ---------- 2x2 area downsample, interleaved layout (output h,w) ----------
__global__ void bp_ds_inter(const float* __restrict__ src, float* __restrict__ dst, int h, int w) {
    int idx = blockIdx.x * blockDim.x + threadIdx.x;
    int total = BB * h * w;
    if (idx >= total) return;
    int x = idx % w; int t = idx / w; int y = t % h; int b = t / h;
    int iw = 2 * w;
    const float* s = src + ((((size_t)b * (2 * h) + 2 * y) * iw + 2 * x) * 3);
    size_t rs = (size_t)iw * 3;
    float a0 = 0.25f * (s[0] + s[3] + s[rs + 0] + s[rs + 3]);
    float a1 = 0.25f * (s[1] + s[4] + s[rs + 1] + s[rs + 4]);
    float a2 = 0.25f * (s[2] + s[5] + s[rs + 2] + s[rs + 5]);
    float* d = dst + (size_t)idx * 3;
    d[0] = a0; d[1] = a1; d[2] = a2;
}

// ---------- 2x2 area downsample, planar layout (output h,w over B*3 maps) ----------
__global__ void bp_ds_planar(const float* __restrict__ src, float* __restrict__ dst, int h, int w) {
    int idx = blockIdx.x * blockDim.x + threadIdx.x;
    int total = BB * 3 * h * w;
    if (idx >= total) return;
    int x = idx % w; int t = idx / w; int y = t % h; int bc = t / h;
    int iw = 2 * w;
    const float* s = src + ((size_t)bc * (2 * h) + 2 * y) * iw + 2 * x;
    dst[idx] = 0.25f * (s[0] + s[1] + s[iw] + s[iw + 1]);
}

// ---------- per-scale loss ----------
__global__ __launch_bounds__(256) void bp_loss(
    const float* __restrict__ ref,   // planar (B,3,h,w)
    const float* __restrict__ tgt0,  // interleaved (B,h,w,3)
    const float* __restrict__ tgt1,
    const float* __restrict__ depth, // (B,1,h,w)
    const float* __restrict__ mask,  // (B,2,h,w)
    int h, int w, int accIdx)
{
    int idx = blockIdx.x * blockDim.x + threadIdx.x;
    int total = BB * h * w;
    float acc = 0.0f;
    if (idx < total) {
        int x = idx % w; int t = idx / w; int y = t % h; int b = t / h;
        float lon = ((x + 0.5f) / (float)w * 2.0f - 1.0f) * PI_F;
        float lat = -((y + 0.5f) / (float)h * 2.0f - 1.0f) * (0.5f * PI_F);
        float slat, clat, slon, clon;
        sincosf(lat, &slat, &clat);
        sincosf(lon, &slon, &clon);
        float d = depth[idx];
        float xx = d * clat * slon;
        float yy = d * slat;
        float zz = d * clat * clon;
        int p = y * w + x;
        int hw = h * w;
        const float* rp = ref + (size_t)b * 3 * hw + p;
        float r0 = rp[0], r1 = rp[hw], r2 = rp[2 * hw];

        #pragma unroll
        for (int n = 0; n < 2; n++) {
            const float* Rm = g_R + (b * 2 + n) * 9;
            const float* tv = g_t + (b * 2 + n) * 3;
            float px = Rm[0] * xx + Rm[1] * yy + Rm[2] * zz + tv[0];
            float py = Rm[3] * xx + Rm[4] * yy + Rm[5] * zz + tv[1];
            float pz = Rm[6] * xx + Rm[7] * yy + Rm[8] * zz + tv[2];
            float nrm = sqrtf(px * px + py * py + pz * pz);
            float lo = atan2f(px, pz);
            float la = asinf(fminf(fmaxf(py / fmaxf(nrm, 1e-8f), -1.0f), 1.0f));
            float gx = lo * (1.0f / PI_F);
            float gy = la * (2.0f / PI_F);
            float fx = (gx + 1.0f) * 0.5f * (float)(w - 1);
            float fy = (gy + 1.0f) * 0.5f * (float)(h - 1);
            float x0f = floorf(fx), y0f = floorf(fy);
            int x0 = (int)x0f, y0 = (int)y0f;
            int x1 = x0 + 1, y1 = y0 + 1;
            float wx1 = fx - x0f, wy1 = fy - y0f;
            float wx0 = 1.0f - wx1, wy0 = 1.0f - wy1;
            bool vx0 = (x0 >= 0) & (x0 < w);
            bool vx1 = (x1 >= 0) & (x1 < w);
            bool vy0 = (y0 >= 0) & (y0 < h);
            bool vy1 = (y1 >= 0) & (y1 < h);
            const float* tg = n ? tgt1 : tgt0;
            float w0 = 0.0f, w1 = 0.0f, w2 = 0.0f;
            if (vx0 & vy0) {
                const float* c = tg + (((size_t)b * h + y0) * w + x0) * 3;
                float wt = wx0 * wy0;
                w0 += wt * c[0]; w1 += wt * c[1]; w2 += wt * c[2];
            }
            if (vx0 & vy1) {
                const float* c = tg + (((size_t)b * h + y1) * w + x0) * 3;
                float wt = wx0 * wy1;
                w0 += wt * c[0]; w1 += wt * c[1]; w2 += wt * c[2];
            }
            if (vx1 & vy0) {
                const float* c = tg + (((size_t)b * h + y0) * w + x1) * 3;
                float wt = wx1 * wy0;
                w0 += wt * c[0]; w1 += wt * c[1]; w2 += wt * c[2];
            }
            if (vx1 & vy1) {
                const float* c = tg + (((size_t)b * h + y1) * w + x1) * 3;
                float wt = wx1 * wy1;
                w0 += wt * c[0]; w1 += wt * c[1]; w2 += wt * c[2];
            }
            float m = mask[((size_t)b * 2 + n) * hw + p];
            acc += m * (fabsf(r0 - w0) + fabsf(r1 - w1) + fabsf(r2 - w2));
        }
    }
    // block reduction
    float v = acc;
    #pragma unroll
    for (int o = 16; o > 0; o >>= 1) v += __shfl_down_sync(0xffffffffu, v, o);
    __shared__ float ws[8];
    int lane = threadIdx.x & 31, warp = threadIdx.x >> 5;
    if (lane == 0) ws[warp] = v;
    __syncthreads();
    if (threadIdx.x == 0) {
        float s = 0.0f;
        #pragma unroll
        for (int i = 0; i < 8; i++) s += ws[i];
        atomicAdd(&g_acc[accIdx], (double)s);
    }
}

__global__ void bp_finalize(float* out) {
    double l = 0.0;
    l += g_acc[0] / (24.0 * 512.0 * 1024.0);
    l += g_acc[1] / (24.0 * 256.0 * 512.0);
    l += g_acc[2] / (24.0 * 128.0 * 256.0);
    l += g_acc[3] / (24.0 * 64.0 * 128.0);
    out[0] = (float)l;
}

extern "C" void kernel_launch(void* const* d_in, const int* in_sizes, int n_in,
                              void* d_out, int out_size) {
    const float* ref_rgb = (const float*)d_in[0];
    const float* depth[4];
    const float* mask[4];
    const float* tgt0;
    const float* tgt1;
    const float* pose;

    // Input-order detection:
    // setup_inputs() dict insertion order is INTERLEAVED:
    //   ref_rgb, depth0, mask0, depth1, mask1, depth2, mask2, depth3, mask3, tgt0, tgt1, pose
    // reference() signature order is GROUPED:
    //   ref_rgb, depth0..3, mask0..3, tgt0, tgt1, pose
    // Distinguish via in_sizes[2]: mask0 = 8*2*512*1024 = 8388608, depth1 = 8*1*256*512 = 1048576.
    if (in_sizes[2] == 8388608) {
        // interleaved
        for (int i = 0; i < 4; i++) {
            depth[i] = (const float*)d_in[1 + 2 * i];
            mask[i]  = (const float*)d_in[2 + 2 * i];
        }
        tgt0 = (const float*)d_in[9];
        tgt1 = (const float*)d_in[10];
        pose = (const float*)d_in[11];
    } else {
        // grouped
        for (int i = 0; i < 4; i++) {
            depth[i] = (const float*)d_in[1 + i];
            mask[i]  = (const float*)d_in[5 + i];
        }
        tgt0 = (const float*)d_in[9];
        tgt1 = (const float*)d_in[10];
        pose = (const float*)d_in[11];
    }
    float* out = (float*)d_out;

    float *p_refds, *p_tgtI0, *p_tgtI1;
    cudaGetSymbolAddress((void**)&p_refds, g_refds);
    cudaGetSymbolAddress((void**)&p_tgtI0, g_tgtI0);
    cudaGetSymbolAddress((void**)&p_tgtI1, g_tgtI1);

    const int TPB = 256;
    // level dims
    const int hs[4] = {512, 256, 128, 64};
    const int ws_[4] = {1024, 512, 256, 128};
    // interleaved tgt level offsets (floats)
    const size_t TOFF[4] = {0, 12582912, 15728640, 16515072};
    // planar ref level offsets for levels 1..3
    const size_t ROFF[4] = {0, 0, 3145728, 3932160};

    bp_pose_init<<<1, 32>>>(pose);

    // tgt transpose level 0
    {
        int total = BB * HH * WW;
        int nb = (total + TPB - 1) / TPB;
        bp_transpose<<<nb, TPB>>>(tgt0, p_tgtI0 + TOFF[0], HH * WW);
        bp_transpose<<<nb, TPB>>>(tgt1, p_tgtI1 + TOFF[0], HH * WW);
    }
    // tgt mip chain (interleaved)
    for (int lvl = 1; lvl < 4; lvl++) {
        int h = hs[lvl], w = ws_[lvl];
        int total = BB * h * w;
        int nb = (total + TPB - 1) / TPB;
        bp_ds_inter<<<nb, TPB>>>(p_tgtI0 + TOFF[lvl - 1], p_tgtI0 + TOFF[lvl], h, w);
        bp_ds_inter<<<nb, TPB>>>(p_tgtI1 + TOFF[lvl - 1], p_tgtI1 + TOFF[lvl], h, w);
    }
    // ref mip chain (planar)
    {
        int h = hs[1], w = ws_[1];
        int total = BB * 3 * h * w;
        bp_ds_planar<<<(total + TPB - 1) / TPB, TPB>>>(ref_rgb, p_refds + ROFF[1], h, w);
    }
    for (int lvl = 2; lvl < 4; lvl++) {
        int h = hs[lvl], w = ws_[lvl];
        int total = BB * 3 * h * w;
        bp_ds_planar<<<(total + TPB - 1) / TPB, TPB>>>(p_refds + ROFF[lvl - 1], p_refds + ROFF[lvl], h, w);
    }

    // loss passes
    for (int lvl = 0; lvl < 4; lvl++) {
        int h = hs[lvl], w = ws_[lvl];
        int total = BB * h * w;
        int nb = (total + TPB - 1) / TPB;
        const float* refp = (lvl == 0) ? ref_rgb : (p_refds + ROFF[lvl]);
        bp_loss<<<nb, TPB>>>(refp, p_tgtI0 + TOFF[lvl], p_tgtI1 + TOFF[lvl],
                             depth[lvl], mask[lvl], h, w, lvl);
    }

    bp_finalize<<<1, 1>>>(out);
    (void)n_in; (void)out_size;
}

// round 3
// speedup vs baseline: 1.3598x; 1.3598x over previous
#include <cuda_runtime.h>
#include <math.h>

#define PI_F 3.14159265358979323846f
#define HPI_F 1.57079632679489662f

#define BB 8
#define HH 512
#define WW 1024

// ---------- static scratch ----------
// tgt interleaved mips (B,h,w,3): L1@0 (3145728), L2@3145728 (786432), L3@3932160 (196608)
__device__ float g_tgtM0[4128768];
__device__ float g_tgtM1[4128768];
// ref planar mips (B,3,h,w): same float offsets
__device__ float g_refM[4128768];
__device__ float g_R[BB * 2 * 9];
__device__ float g_t[BB * 2 * 3];
// sincos tables: lon (slon,clon) sizes 1024,512,256,128 @ offs 0,1024,1536,1792
//                lat (slat,clat) sizes 512,256,128,64  @ offs 0,512,768,896
__device__ float2 g_lonT[1920];
__device__ float2 g_latT[960];
__device__ double g_acc[4];

// ---------- init: pose -> R,t ; tables ; zero acc ----------
__global__ void bp_init(const float* __restrict__ pose) {
    int tid = threadIdx.x;
    if (tid < 4) g_acc[tid] = 0.0;
    if (tid < BB * 2) {
        const float* p = pose + tid * 6;
        float rx = p[3], ry = p[4], rz = p[5];
        float th = sqrtf(rx * rx + ry * ry + rz * rz);
        float inv = 1.0f / fmaxf(th, 1e-8f);
        float kx = rx * inv, ky = ry * inv, kz = rz * inv;
        float s = sinf(th), c = cosf(th), ic = 1.0f - c;
        float* R = g_R + tid * 9;
        R[0] = c + ic * kx * kx;      R[1] = ic * kx * ky - s * kz; R[2] = ic * kx * kz + s * ky;
        R[3] = ic * ky * kx + s * kz; R[4] = c + ic * ky * ky;      R[5] = ic * ky * kz - s * kx;
        R[6] = ic * kz * kx - s * ky; R[7] = ic * kz * ky + s * kx; R[8] = c + ic * kz * kz;
        float* t = g_t + tid * 3;
        t[0] = p[0]; t[1] = p[1]; t[2] = p[2];
    }
    for (int i = tid; i < 1920; i += 256) {
        int off, w;
        if (i < 1024)      { off = 0;    w = 1024; }
        else if (i < 1536) { off = 1024; w = 512; }
        else if (i < 1792) { off = 1536; w = 256; }
        else               { off = 1792; w = 128; }
        int xi = i - off;
        float lon = ((xi + 0.5f) / (float)w * 2.0f - 1.0f) * PI_F;
        g_lonT[i] = make_float2(sinf(lon), cosf(lon));
    }
    for (int i = tid; i < 960; i += 256) {
        int off, h;
        if (i < 512)      { off = 0;   h = 512; }
        else if (i < 768) { off = 512; h = 256; }
        else if (i < 896) { off = 768; h = 128; }
        else              { off = 896; h = 64; }
        int yi = i - off;
        float lat = -((yi + 0.5f) / (float)h * 2.0f - 1.0f) * HPI_F;
        g_latT[i] = make_float2(sinf(lat), cosf(lat));
    }
}

// ---------- fast atan poly on [0,1], max err ~1e-5 rad ----------
__device__ __forceinline__ float atanp(float r) {
    float z = r * r;
    float p = -0.0117212f;
    p = fmaf(p, z, 0.05265332f);
    p = fmaf(p, z, -0.11643287f);
    p = fmaf(p, z, 0.19354346f);
    p = fmaf(p, z, -0.33262347f);
    p = fmaf(p, z, 0.99997726f);
    return r * p;
}

// ---------- one warped-frame L1 term ----------
template <bool PLANAR>
__device__ __forceinline__ float warp_term(
    const float* __restrict__ tg, int b, int h, int w,
    float px, float py, float pz,
    float r0, float r1, float r2, float m)
{
    // lon = atan2(px, pz)
    float ax = fabsf(px), az = fabsf(pz);
    float mn = fminf(ax, az), mx = fmaxf(ax, az);
    float t = atanp(__fdividef(mn, mx));
    t = (ax > az) ? (HPI_F - t) : t;
    t = (pz < 0.0f) ? (PI_F - t) : t;
    float lo = copysignf(t, px);
    // lat = asin(py/norm) = atan2(py, sqrt(px^2+pz^2))
    float q = py * py;
    float s2 = fmaf(px, px, pz * pz);
    float mn2 = fminf(q, s2), mx2 = fmaxf(q, s2);
    float t2 = atanp(sqrtf(__fdividef(mn2, mx2)));
    t2 = (q > s2) ? (HPI_F - t2) : t2;
    float la = copysignf(t2, py);

    float fx = (lo * (1.0f / PI_F) + 1.0f) * (0.5f * (float)(w - 1));
    float fy = (la * (2.0f / PI_F) + 1.0f) * (0.5f * (float)(h - 1));
    float x0f = floorf(fx), y0f = floorf(fy);
    float wx1 = fx - x0f, wy1 = fy - y0f;
    float wx0 = 1.0f - wx1, wy0 = 1.0f - wy1;
    int x0 = (int)x0f, y0 = (int)y0f;
    int x1 = min(x0 + 1, w - 1), y1 = min(y0 + 1, h - 1);
    x0 = max(min(x0, w - 1), 0); y0 = max(min(y0, h - 1), 0);
    x1 = max(x1, 0); y1 = max(y1, 0);
    float wa = wx0 * wy0, wb = wx0 * wy1, wc = wx1 * wy0, wd = wx1 * wy1;

    float w0, w1, w2;
    if (PLANAR) {
        int hw = h * w;
        const float* base = tg + (size_t)b * 3 * hw;
        int i00 = y0 * w + x0, i01 = y1 * w + x0, i10 = y0 * w + x1, i11 = y1 * w + x1;
        w0 = wa * __ldg(base + i00) + wb * __ldg(base + i01) + wc * __ldg(base + i10) + wd * __ldg(base + i11);
        base += hw;
        w1 = wa * __ldg(base + i00) + wb * __ldg(base + i01) + wc * __ldg(base + i10) + wd * __ldg(base + i11);
        base += hw;
        w2 = wa * __ldg(base + i00) + wb * __ldg(base + i01) + wc * __ldg(base + i10) + wd * __ldg(base + i11);
    } else {
        const float* ra = tg + (size_t)(b * h + y0) * w * 3;
        const float* rb = tg + (size_t)(b * h + y1) * w * 3;
        const float* c00 = ra + x0 * 3; const float* c10 = ra + x1 * 3;
        const float* c01 = rb + x0 * 3; const float* c11 = rb + x1 * 3;
        w0 = wa * __ldg(c00 + 0) + wb * __ldg(c01 + 0) + wc * __ldg(c10 + 0) + wd * __ldg(c11 + 0);
        w1 = wa * __ldg(c00 + 1) + wb * __ldg(c01 + 1) + wc * __ldg(c10 + 1) + wd * __ldg(c11 + 1);
        w2 = wa * __ldg(c00 + 2) + wb * __ldg(c01 + 2) + wc * __ldg(c10 + 2) + wd * __ldg(c11 + 2);
    }
    return m * (fabsf(r0 - w0) + fabsf(r1 - w1) + fabsf(r2 - w2));
}

__device__ __forceinline__ void block_reduce_add(float v, int accIdx) {
    #pragma unroll
    for (int o = 16; o > 0; o >>= 1) v += __shfl_down_sync(0xffffffffu, v, o);
    __shared__ float ws[8];
    int lane = threadIdx.x & 31, warp = threadIdx.x >> 5;
    if (lane == 0) ws[warp] = v;
    __syncthreads();
    if (threadIdx.x == 0) {
        float s = 0.0f;
        #pragma unroll
        for (int i = 0; i < 8; i++) s += ws[i];
        atomicAdd(&g_acc[accIdx], (double)s);
    }
}

// ---------- loss level 0: gathers directly from planar inputs ----------
__global__ __launch_bounds__(256) void bp_loss0(
    const float* __restrict__ ref, const float* __restrict__ tgt0,
    const float* __restrict__ tgt1, const float* __restrict__ depth,
    const float* __restrict__ mask)
{
    int idx = blockIdx.x * 256 + threadIdx.x;
    int x = idx & 1023, y = (idx >> 10) & 511, b = idx >> 19;
    float2 lc = g_lonT[x];
    float2 lt = g_latT[y];
    float d = __ldg(depth + idx);
    float xx = d * lt.y * lc.x;
    float yy = d * lt.x;
    float zz = d * lt.y * lc.y;
    const int hw = 512 * 1024;
    int p = y * 1024 + x;
    const float* rp = ref + (size_t)b * 3 * hw + p;
    float r0 = __ldg(rp), r1 = __ldg(rp + hw), r2 = __ldg(rp + 2 * hw);
    float acc = 0.0f;
    #pragma unroll
    for (int n = 0; n < 2; n++) {
        const float* Rm = g_R + (b * 2 + n) * 9;
        const float* tv = g_t + (b * 2 + n) * 3;
        float px = __ldg(Rm+0) * xx + __ldg(Rm+1) * yy + __ldg(Rm+2) * zz + __ldg(tv+0);
        float py = __ldg(Rm+3) * xx + __ldg(Rm+4) * yy + __ldg(Rm+5) * zz + __ldg(tv+1);
        float pz = __ldg(Rm+6) * xx + __ldg(Rm+7) * yy + __ldg(Rm+8) * zz + __ldg(tv+2);
        float m = __ldg(mask + (size_t)(b * 2 + n) * hw + p);
        acc += warp_term<true>(n ? tgt1 : tgt0, b, 512, 1024, px, py, pz, r0, r1, r2, m);
    }
    block_reduce_add(acc, 0);
}

// ---------- loss levels 1..3 merged ----------
__global__ __launch_bounds__(256) void bp_loss123(
    const float* __restrict__ d1, const float* __restrict__ m1,
    const float* __restrict__ d2, const float* __restrict__ m2,
    const float* __restrict__ d3, const float* __restrict__ m3)
{
    int blk = blockIdx.x;
    const float *dep, *msk;
    int h, w, lw, lh, lonO, latO, accI, base;
    size_t toff;
    if (blk < 4096)      { dep = d1; msk = m1; h = 256; w = 512; lw = 9; lh = 8; lonO = 1024; latO = 512; toff = 0;       accI = 1; base = 0; }
    else if (blk < 5120) { dep = d2; msk = m2; h = 128; w = 256; lw = 8; lh = 7; lonO = 1536; latO = 768; toff = 3145728; accI = 2; base = 4096; }
    else                 { dep = d3; msk = m3; h = 64;  w = 128; lw = 7; lh = 6; lonO = 1792; latO = 896; toff = 3932160; accI = 3; base = 5120; }
    int idx = (blk - base) * 256 + threadIdx.x;
    int x = idx & (w - 1), y = (idx >> lw) & (h - 1), b = idx >> (lw + lh);
    float2 lc = g_lonT[lonO + x];
    float2 lt = g_latT[latO + y];
    float d = __ldg(dep + idx);
    float xx = d * lt.y * lc.x;
    float yy = d * lt.x;
    float zz = d * lt.y * lc.y;
    int hw = h * w;
    int p = y * w + x;
    const float* rp = g_refM + toff + (size_t)b * 3 * hw + p;
    float r0 = rp[0], r1 = rp[hw], r2 = rp[2 * hw];
    const float* tg0 = g_tgtM0 + toff;
    const float* tg1 = g_tgtM1 + toff;
    float acc = 0.0f;
    #pragma unroll
    for (int n = 0; n < 2; n++) {
        const float* Rm = g_R + (b * 2 + n) * 9;
        const float* tv = g_t + (b * 2 + n) * 3;
        float px = __ldg(Rm+0) * xx + __ldg(Rm+1) * yy + __ldg(Rm+2) * zz + __ldg(tv+0);
        float py = __ldg(Rm+3) * xx + __ldg(Rm+4) * yy + __ldg(Rm+5) * zz + __ldg(tv+1);
        float pz = __ldg(Rm+6) * xx + __ldg(Rm+7) * yy + __ldg(Rm+8) * zz + __ldg(tv+2);
        float m = __ldg(msk + (size_t)(b * 2 + n) * hw + p);
        acc += warp_term<false>(n ? tg1 : tg0, b, h, w, px, py, pz, r0, r1, r2, m);
    }
    block_reduce_add(acc, accI);
}

// ---------- prep1: planar L0 -> interleaved tgt L1 (both) + planar ref L1 ----------
__global__ __launch_bounds__(256) void bp_prep1(
    const float* __restrict__ tgt0, const float* __restrict__ tgt1,
    const float* __restrict__ ref)
{
    int blk = blockIdx.x;
    if (blk < 8192) {
        const float* src = (blk < 4096) ? tgt0 : tgt1;
        float* dst = (blk < 4096) ? g_tgtM0 : g_tgtM1;
        int idx = (blk & 4095) * 256 + threadIdx.x;          // [0, 1048576)
        int x = idx & 511, y = (idx >> 9) & 255, b = idx >> 17;
        float a[3];
        #pragma unroll
        for (int c = 0; c < 3; c++) {
            const float* r0 = src + (((size_t)(b * 3 + c) * 512 + 2 * y) * 1024 + 2 * x);
            float2 u0 = *(const float2*)r0;
            float2 u1 = *(const float2*)(r0 + 1024);
            a[c] = 0.25f * (u0.x + u0.y + u1.x + u1.y);
        }
        float* o = dst + (size_t)((b * 256 + y) * 512 + x) * 3;
        o[0] = a[0]; o[1] = a[1]; o[2] = a[2];
    } else {
        int j = (blk - 8192) * 256 + threadIdx.x;            // [0, 3145728)
        int x = j & 511, y = (j >> 9) & 255, pp = j >> 17;
        const float* r0 = ref + (((size_t)pp * 512 + 2 * y) * 1024 + 2 * x);
        float2 u0 = *(const float2*)r0;
        float2 u1 = *(const float2*)(r0 + 1024);
        g_refM[j] = 0.25f * (u0.x + u0.y + u1.x + u1.y);
    }
}

// ---------- prep2: L1 -> L2 ----------
__global__ __launch_bounds__(256) void bp_prep2() {
    int blk = blockIdx.x;
    if (blk < 2048) {
        float* M = (blk < 1024) ? g_tgtM0 : g_tgtM1;
        int idx = (blk & 1023) * 256 + threadIdx.x;          // [0, 262144)
        int x = idx & 255, y = (idx >> 8) & 127, b = idx >> 15;
        const float* s0 = M + (size_t)((b * 256 + 2 * y) * 512 + 2 * x) * 3;
        const float* s1 = s0 + 512 * 3;
        float2 a0 = *(const float2*)(s0), a1 = *(const float2*)(s0 + 2), a2 = *(const float2*)(s0 + 4);
        float2 b0 = *(const float2*)(s1), b1 = *(const float2*)(s1 + 2), b2 = *(const float2*)(s1 + 4);
        float c0 = 0.25f * (a0.x + a1.y + b0.x + b1.y);
        float c1 = 0.25f * (a0.y + a2.x + b0.y + b2.x);
        float c2 = 0.25f * (a1.x + a2.y + b1.x + b2.y);
        float* o = M + 3145728 + (size_t)((b * 128 + y) * 256 + x) * 3;
        o[0] = c0; o[1] = c1; o[2] = c2;
    } else {
        int j = (blk - 2048) * 256 + threadIdx.x;            // [0, 786432)
        int x = j & 255, y = (j >> 8) & 127, pp = j >> 15;
        const float* s = g_refM + ((size_t)pp * 256 + 2 * y) * 512 + 2 * x;
        float2 u0 = *(const float2*)s, u1 = *(const float2*)(s + 512);
        g_refM[3145728 + j] = 0.25f * (u0.x + u0.y + u1.x + u1.y);
    }
}

// ---------- prep3: L2 -> L3 ----------
__global__ __launch_bounds__(256) void bp_prep3() {
    int blk = blockIdx.x;
    if (blk < 512) {
        float* M = (blk < 256) ? g_tgtM0 : g_tgtM1;
        int idx = (blk & 255) * 256 + threadIdx.x;           // [0, 65536)
        int x = idx & 127, y = (idx >> 7) & 63, b = idx >> 13;
        const float* s0 = M + 3145728 + (size_t)((b * 128 + 2 * y) * 256 + 2 * x) * 3;
        const float* s1 = s0 + 256 * 3;
        float2 a0 = *(const float2*)(s0), a1 = *(const float2*)(s0 + 2), a2 = *(const float2*)(s0 + 4);
        float2 b0 = *(const float2*)(s1), b1 = *(const float2*)(s1 + 2), b2 = *(const float2*)(s1 + 4);
        float c0 = 0.25f * (a0.x + a1.y + b0.x + b1.y);
        float c1 = 0.25f * (a0.y + a2.x + b0.y + b2.x);
        float c2 = 0.25f * (a1.x + a2.y + b1.x + b2.y);
        float* o = M + 3932160 + (size_t)((b * 64 + y) * 128 + x) * 3;
        o[0] = c0; o[1] = c1; o[2] = c2;
    } else {
        int j = (blk - 512) * 256 + threadIdx.x;             // [0, 196608)
        int x = j & 127, y = (j >> 7) & 63, pp = j >> 13;
        const float* s = g_refM + 3145728 + ((size_t)pp * 128 + 2 * y) * 256 + 2 * x;
        float2 u0 = *(const float2*)s, u1 = *(const float2*)(s + 256);
        g_refM[3932160 + j] = 0.25f * (u0.x + u0.y + u1.x + u1.y);
    }
}

__global__ void bp_finalize(float* out) {
    double l = 0.0;
    l += g_acc[0] / (24.0 * 512.0 * 1024.0);
    l += g_acc[1] / (24.0 * 256.0 * 512.0);
    l += g_acc[2] / (24.0 * 128.0 * 256.0);
    l += g_acc[3] / (24.0 * 64.0 * 128.0);
    out[0] = (float)l;
}

extern "C" void kernel_launch(void* const* d_in, const int* in_sizes, int n_in,
                              void* d_out, int out_size) {
    const float* ref_rgb = (const float*)d_in[0];
    const float* depth[4];
    const float* mask[4];
    // Input-order detection: interleaved (dict order) vs grouped (signature order).
    // in_sizes[2]: mask0 = 8388608 (interleaved) vs depth1 = 1048576 (grouped).
    if (in_sizes[2] == 8388608) {
        for (int i = 0; i < 4; i++) {
            depth[i] = (const float*)d_in[1 + 2 * i];
            mask[i]  = (const float*)d_in[2 + 2 * i];
        }
    } else {
        for (int i = 0; i < 4; i++) {
            depth[i] = (const float*)d_in[1 + i];
            mask[i]  = (const float*)d_in[5 + i];
        }
    }
    const float* tgt0 = (const float*)d_in[9];
    const float* tgt1 = (const float*)d_in[10];
    const float* pose = (const float*)d_in[11];
    float* out = (float*)d_out;

    bp_init<<<1, 256>>>(pose);
    bp_loss0<<<16384, 256>>>(ref_rgb, tgt0, tgt1, depth[0], mask[0]);
    bp_prep1<<<20480, 256>>>(tgt0, tgt1, ref_rgb);
    bp_prep2<<<5120, 256>>>();
    bp_prep3<<<1280, 256>>>();
    bp_loss123<<<5376, 256>>>(depth[1], mask[1], depth[2], mask[2], depth[3], mask[3]);
    bp_finalize<<<1, 1>>>(out);
    (void)n_in; (void)out_size;
}

// round 4
// speedup vs baseline: 1.4528x; 1.0684x over previous
#include <cuda_runtime.h>
#include <math.h>

#define PI_F 3.14159265358979323846f
#define HPI_F 1.57079632679489662f

#define BB 8
#define HH 512
#define WW 1024

// ---------- static scratch ----------
// tgt interleaved mips (B,h,w,3): L1@0 (3145728), L2@3145728 (786432), L3@3932160 (196608)
__device__ float g_tgtM0[4128768];
__device__ float g_tgtM1[4128768];
// ref planar mips (B,3,h,w): same float offsets
__device__ float g_refM[4128768];
__device__ float g_R[BB * 2 * 9];
__device__ float g_t[BB * 2 * 3];
// sincos tables: lon sizes 1024,512,256,128 @ offs 0,1024,1536,1792
//                lat sizes 512,256,128,64  @ offs 0,512,768,896
__device__ float2 g_lonT[1920];
__device__ float2 g_latT[960];
__device__ double g_acc[4];

// ---------- init ----------
__global__ void bp_init(const float* __restrict__ pose) {
    int tid = threadIdx.x;
    if (tid < 4) g_acc[tid] = 0.0;
    if (tid < BB * 2) {
        const float* p = pose + tid * 6;
        float rx = p[3], ry = p[4], rz = p[5];
        float th = sqrtf(rx * rx + ry * ry + rz * rz);
        float inv = 1.0f / fmaxf(th, 1e-8f);
        float kx = rx * inv, ky = ry * inv, kz = rz * inv;
        float s = sinf(th), c = cosf(th), ic = 1.0f - c;
        float* R = g_R + tid * 9;
        R[0] = c + ic * kx * kx;      R[1] = ic * kx * ky - s * kz; R[2] = ic * kx * kz + s * ky;
        R[3] = ic * ky * kx + s * kz; R[4] = c + ic * ky * ky;      R[5] = ic * ky * kz - s * kx;
        R[6] = ic * kz * kx - s * ky; R[7] = ic * kz * ky + s * kx; R[8] = c + ic * kz * kz;
        float* t = g_t + tid * 3;
        t[0] = p[0]; t[1] = p[1]; t[2] = p[2];
    }
    for (int i = tid; i < 1920; i += 256) {
        int off, w;
        if (i < 1024)      { off = 0;    w = 1024; }
        else if (i < 1536) { off = 1024; w = 512; }
        else if (i < 1792) { off = 1536; w = 256; }
        else               { off = 1792; w = 128; }
        int xi = i - off;
        float lon = ((xi + 0.5f) / (float)w * 2.0f - 1.0f) * PI_F;
        g_lonT[i] = make_float2(sinf(lon), cosf(lon));
    }
    for (int i = tid; i < 960; i += 256) {
        int off, h;
        if (i < 512)      { off = 0;   h = 512; }
        else if (i < 768) { off = 512; h = 256; }
        else if (i < 896) { off = 768; h = 128; }
        else              { off = 896; h = 64; }
        int yi = i - off;
        float lat = -((yi + 0.5f) / (float)h * 2.0f - 1.0f) * HPI_F;
        g_latT[i] = make_float2(sinf(lat), cosf(lat));
    }
}

// ---------- fast atan poly on [0,1], max err ~1e-5 rad ----------
__device__ __forceinline__ float atanp(float r) {
    float z = r * r;
    float p = -0.0117212f;
    p = fmaf(p, z, 0.05265332f);
    p = fmaf(p, z, -0.11643287f);
    p = fmaf(p, z, 0.19354346f);
    p = fmaf(p, z, -0.33262347f);
    p = fmaf(p, z, 0.99997726f);
    return r * p;
}

// ---------- one warped-frame L1 term ----------
template <bool PLANAR>
__device__ __forceinline__ float warp_term(
    const float* __restrict__ tg, int b, int h, int w,
    float px, float py, float pz,
    float r0, float r1, float r2, float m)
{
    float ax = fabsf(px), az = fabsf(pz);
    float mn = fminf(ax, az), mx = fmaxf(ax, az);
    float t = atanp(__fdividef(mn, mx));
    t = (ax > az) ? (HPI_F - t) : t;
    t = (pz < 0.0f) ? (PI_F - t) : t;
    float lo = copysignf(t, px);
    float q = py * py;
    float s2 = fmaf(px, px, pz * pz);
    float mn2 = fminf(q, s2), mx2 = fmaxf(q, s2);
    float t2 = atanp(sqrtf(__fdividef(mn2, mx2)));
    t2 = (q > s2) ? (HPI_F - t2) : t2;
    float la = copysignf(t2, py);

    float fx = (lo * (1.0f / PI_F) + 1.0f) * (0.5f * (float)(w - 1));
    float fy = (la * (2.0f / PI_F) + 1.0f) * (0.5f * (float)(h - 1));
    float x0f = floorf(fx), y0f = floorf(fy);
    float wx1 = fx - x0f, wy1 = fy - y0f;
    float wx0 = 1.0f - wx1, wy0 = 1.0f - wy1;
    int x0 = (int)x0f, y0 = (int)y0f;
    int x1 = min(x0 + 1, w - 1), y1 = min(y0 + 1, h - 1);
    x0 = max(min(x0, w - 1), 0); y0 = max(min(y0, h - 1), 0);
    x1 = max(x1, 0); y1 = max(y1, 0);
    float wa = wx0 * wy0, wb = wx0 * wy1, wc = wx1 * wy0, wd = wx1 * wy1;

    float w0, w1, w2;
    if (PLANAR) {
        int hw = h * w;
        const float* base = tg + (size_t)b * 3 * hw;
        int i00 = y0 * w + x0, i01 = y1 * w + x0, i10 = y0 * w + x1, i11 = y1 * w + x1;
        w0 = wa * __ldg(base + i00) + wb * __ldg(base + i01) + wc * __ldg(base + i10) + wd * __ldg(base + i11);
        base += hw;
        w1 = wa * __ldg(base + i00) + wb * __ldg(base + i01) + wc * __ldg(base + i10) + wd * __ldg(base + i11);
        base += hw;
        w2 = wa * __ldg(base + i00) + wb * __ldg(base + i01) + wc * __ldg(base + i10) + wd * __ldg(base + i11);
    } else {
        const float* ra = tg + (size_t)(b * h + y0) * w * 3;
        const float* rb = tg + (size_t)(b * h + y1) * w * 3;
        const float* c00 = ra + x0 * 3; const float* c10 = ra + x1 * 3;
        const float* c01 = rb + x0 * 3; const float* c11 = rb + x1 * 3;
        w0 = wa * __ldg(c00 + 0) + wb * __ldg(c01 + 0) + wc * __ldg(c10 + 0) + wd * __ldg(c11 + 0);
        w1 = wa * __ldg(c00 + 1) + wb * __ldg(c01 + 1) + wc * __ldg(c10 + 1) + wd * __ldg(c11 + 1);
        w2 = wa * __ldg(c00 + 2) + wb * __ldg(c01 + 2) + wc * __ldg(c10 + 2) + wd * __ldg(c11 + 2);
    }
    return m * (fabsf(r0 - w0) + fabsf(r1 - w1) + fabsf(r2 - w2));
}

__device__ __forceinline__ void block_reduce_add(float v, int accIdx) {
    #pragma unroll
    for (int o = 16; o > 0; o >>= 1) v += __shfl_down_sync(0xffffffffu, v, o);
    __shared__ float ws[8];
    int lane = threadIdx.x & 31, warp = threadIdx.x >> 5;
    if (lane == 0) ws[warp] = v;
    __syncthreads();
    if (threadIdx.x == 0) {
        float s = 0.0f;
        #pragma unroll
        for (int i = 0; i < 8; i++) s += ws[i];
        atomicAdd(&g_acc[accIdx], (double)s);
    }
}

// ---------- FUSED: loss level 0 + build all L1 mips ----------
// One thread per 2x2 L0 block. Dense-loads ref/tgt/depth/mask once:
//   - emits ref L1 (planar) + tgt L1 (interleaved, both frames)
//   - computes the 4 L0 loss terms for both frames (gathers hit L2)
__global__ __launch_bounds__(256) void bp_fused0(
    const float* __restrict__ ref, const float* __restrict__ tgt0,
    const float* __restrict__ tgt1, const float* __restrict__ depth,
    const float* __restrict__ mask)
{
    int idx = blockIdx.x * 256 + threadIdx.x;     // [0, 1048576)
    int x2 = idx & 511, y2 = (idx >> 9) & 255, b = idx >> 17;
    int y0r = 2 * y2;
    int xc = 2 * x2;

    // ---- dense ref load (3 planes x 2 rows x float2) + L1 write ----
    float rv[3][2][2];
    {
        #pragma unroll
        for (int c = 0; c < 3; c++) {
            const float* rp = ref + (((size_t)(b * 3 + c) * 512 + y0r) * 1024 + xc);
            float2 u0 = *(const float2*)rp;
            float2 u1 = *(const float2*)(rp + 1024);
            rv[c][0][0] = u0.x; rv[c][0][1] = u0.y;
            rv[c][1][0] = u1.x; rv[c][1][1] = u1.y;
            g_refM[(size_t)c * 131072 + (size_t)b * 393216 + y2 * 512 + x2] =
                0.25f * (u0.x + u0.y + u1.x + u1.y);
        }
    }
    // ---- dense tgt loads + interleaved L1 writes ----
    {
        float a0[3], a1[3];
        #pragma unroll
        for (int c = 0; c < 3; c++) {
            const float* tp = tgt0 + (((size_t)(b * 3 + c) * 512 + y0r) * 1024 + xc);
            float2 u0 = *(const float2*)tp;
            float2 u1 = *(const float2*)(tp + 1024);
            a0[c] = 0.25f * (u0.x + u0.y + u1.x + u1.y);
            tp = tgt1 + (((size_t)(b * 3 + c) * 512 + y0r) * 1024 + xc);
            u0 = *(const float2*)tp;
            u1 = *(const float2*)(tp + 1024);
            a1[c] = 0.25f * (u0.x + u0.y + u1.x + u1.y);
        }
        float* o0 = g_tgtM0 + (size_t)((b * 256 + y2) * 512 + x2) * 3;
        o0[0] = a0[0]; o0[1] = a0[1]; o0[2] = a0[2];
        float* o1 = g_tgtM1 + (size_t)((b * 256 + y2) * 512 + x2) * 3;
        o1[0] = a1[0]; o1[1] = a1[1]; o1[2] = a1[2];
    }
    // ---- depth & mask dense loads ----
    float2 dR[2];
    float2 mR[2][2];
    {
        const float* dp = depth + ((size_t)b * 512 + y0r) * 1024 + xc;
        dR[0] = *(const float2*)dp;
        dR[1] = *(const float2*)(dp + 1024);
        #pragma unroll
        for (int n = 0; n < 2; n++) {
            const float* mp = mask + (((size_t)(b * 2 + n) * 512 + y0r) * 1024 + xc);
            mR[n][0] = *(const float2*)mp;
            mR[n][1] = *(const float2*)(mp + 1024);
        }
    }
    // ---- rotation rows for this batch ----
    float Rm[2][9], tv[2][3];
    #pragma unroll
    for (int n = 0; n < 2; n++) {
        const float* Rp = g_R + (b * 2 + n) * 9;
        #pragma unroll
        for (int k = 0; k < 9; k++) Rm[n][k] = Rp[k];
        const float* tp = g_t + (b * 2 + n) * 3;
        tv[n][0] = tp[0]; tv[n][1] = tp[1]; tv[n][2] = tp[2];
    }

    float acc = 0.0f;
    #pragma unroll
    for (int dy = 0; dy < 2; dy++) {
        float2 lt = g_latT[y0r + dy];
        #pragma unroll
        for (int dx = 0; dx < 2; dx++) {
            float2 lc = g_lonT[xc + dx];
            float d = (dx == 0) ? dR[dy].x : dR[dy].y;
            float xx = d * lt.y * lc.x;
            float yy = d * lt.x;
            float zz = d * lt.y * lc.y;
            float r0 = rv[0][dy][dx], r1 = rv[1][dy][dx], r2 = rv[2][dy][dx];
            #pragma unroll
            for (int n = 0; n < 2; n++) {
                float px = Rm[n][0] * xx + Rm[n][1] * yy + Rm[n][2] * zz + tv[n][0];
                float py = Rm[n][3] * xx + Rm[n][4] * yy + Rm[n][5] * zz + tv[n][1];
                float pz = Rm[n][6] * xx + Rm[n][7] * yy + Rm[n][8] * zz + tv[n][2];
                float m = (dx == 0) ? mR[n][dy].x : mR[n][dy].y;
                acc += warp_term<true>(n ? tgt1 : tgt0, b, 512, 1024, px, py, pz, r0, r1, r2, m);
            }
        }
    }
    block_reduce_add(acc, 0);
}

// ---------- loss levels 1..3 merged ----------
__global__ __launch_bounds__(256) void bp_loss123(
    const float* __restrict__ d1, const float* __restrict__ m1,
    const float* __restrict__ d2, const float* __restrict__ m2,
    const float* __restrict__ d3, const float* __restrict__ m3)
{
    int blk = blockIdx.x;
    const float *dep, *msk;
    int h, w, lw, lh, lonO, latO, accI, base;
    size_t toff;
    if (blk < 4096)      { dep = d1; msk = m1; h = 256; w = 512; lw = 9; lh = 8; lonO = 1024; latO = 512; toff = 0;       accI = 1; base = 0; }
    else if (blk < 5120) { dep = d2; msk = m2; h = 128; w = 256; lw = 8; lh = 7; lonO = 1536; latO = 768; toff = 3145728; accI = 2; base = 4096; }
    else                 { dep = d3; msk = m3; h = 64;  w = 128; lw = 7; lh = 6; lonO = 1792; latO = 896; toff = 3932160; accI = 3; base = 5120; }
    int idx = (blk - base) * 256 + threadIdx.x;
    int x = idx & (w - 1), y = (idx >> lw) & (h - 1), b = idx >> (lw + lh);
    float2 lc = g_lonT[lonO + x];
    float2 lt = g_latT[latO + y];
    float d = __ldg(dep + idx);
    float xx = d * lt.y * lc.x;
    float yy = d * lt.x;
    float zz = d * lt.y * lc.y;
    int hw = h * w;
    int p = y * w + x;
    const float* rp = g_refM + toff + (size_t)b * 3 * hw + p;
    float r0 = rp[0], r1 = rp[hw], r2 = rp[2 * hw];
    const float* tg0 = g_tgtM0 + toff;
    const float* tg1 = g_tgtM1 + toff;
    float acc = 0.0f;
    #pragma unroll
    for (int n = 0; n < 2; n++) {
        const float* Rm = g_R + (b * 2 + n) * 9;
        const float* tv = g_t + (b * 2 + n) * 3;
        float px = __ldg(Rm+0) * xx + __ldg(Rm+1) * yy + __ldg(Rm+2) * zz + __ldg(tv+0);
        float py = __ldg(Rm+3) * xx + __ldg(Rm+4) * yy + __ldg(Rm+5) * zz + __ldg(tv+1);
        float pz = __ldg(Rm+6) * xx + __ldg(Rm+7) * yy + __ldg(Rm+8) * zz + __ldg(tv+2);
        float m = __ldg(msk + (size_t)(b * 2 + n) * hw + p);
        acc += warp_term<false>(n ? tg1 : tg0, b, h, w, px, py, pz, r0, r1, r2, m);
    }
    block_reduce_add(acc, accI);
}

// ---------- prep2: L1 -> L2 ----------
__global__ __launch_bounds__(256) void bp_prep2() {
    int blk = blockIdx.x;
    if (blk < 2048) {
        float* M = (blk < 1024) ? g_tgtM0 : g_tgtM1;
        int idx = (blk & 1023) * 256 + threadIdx.x;
        int x = idx & 255, y = (idx >> 8) & 127, b = idx >> 15;
        const float* s0 = M + (size_t)((b * 256 + 2 * y) * 512 + 2 * x) * 3;
        const float* s1 = s0 + 512 * 3;
        float2 a0 = *(const float2*)(s0), a1 = *(const float2*)(s0 + 2), a2 = *(const float2*)(s0 + 4);
        float2 b0 = *(const float2*)(s1), b1 = *(const float2*)(s1 + 2), b2 = *(const float2*)(s1 + 4);
        float c0 = 0.25f * (a0.x + a1.y + b0.x + b1.y);
        float c1 = 0.25f * (a0.y + a2.x + b0.y + b2.x);
        float c2 = 0.25f * (a1.x + a2.y + b1.x + b2.y);
        float* o = M + 3145728 + (size_t)((b * 128 + y) * 256 + x) * 3;
        o[0] = c0; o[1] = c1; o[2] = c2;
    } else {
        int j = (blk - 2048) * 256 + threadIdx.x;
        int x = j & 255, y = (j >> 8) & 127, pp = j >> 15;
        const float* s = g_refM + ((size_t)pp * 256 + 2 * y) * 512 + 2 * x;
        float2 u0 = *(const float2*)s, u1 = *(const float2*)(s + 512);
        g_refM[3145728 + j] = 0.25f * (u0.x + u0.y + u1.x + u1.y);
    }
}

// ---------- prep3: L2 -> L3 ----------
__global__ __launch_bounds__(256) void bp_prep3() {
    int blk = blockIdx.x;
    if (blk < 512) {
        float* M = (blk < 256) ? g_tgtM0 : g_tgtM1;
        int idx = (blk & 255) * 256 + threadIdx.x;
        int x = idx & 127, y = (idx >> 7) & 63, b = idx >> 13;
        const float* s0 = M + 3145728 + (size_t)((b * 128 + 2 * y) * 256 + 2 * x) * 3;
        const float* s1 = s0 + 256 * 3;
        float2 a0 = *(const float2*)(s0), a1 = *(const float2*)(s0 + 2), a2 = *(const float2*)(s0 + 4);
        float2 b0 = *(const float2*)(s1), b1 = *(const float2*)(s1 + 2), b2 = *(const float2*)(s1 + 4);
        float c0 = 0.25f * (a0.x + a1.y + b0.x + b1.y);
        float c1 = 0.25f * (a0.y + a2.x + b0.y + b2.x);
        float c2 = 0.25f * (a1.x + a2.y + b1.x + b2.y);
        float* o = M + 3932160 + (size_t)((b * 64 + y) * 128 + x) * 3;
        o[0] = c0; o[1] = c1; o[2] = c2;
    } else {
        int j = (blk - 512) * 256 + threadIdx.x;
        int x = j & 127, y = (j >> 7) & 63, pp = j >> 13;
        const float* s = g_refM + 3145728 + ((size_t)pp * 128 + 2 * y) * 256 + 2 * x;
        float2 u0 = *(const float2*)s, u1 = *(const float2*)(s + 256);
        g_refM[3932160 + j] = 0.25f * (u0.x + u0.y + u1.x + u1.y);
    }
}

__global__ void bp_finalize(float* out) {
    double l = 0.0;
    l += g_acc[0] / (24.0 * 512.0 * 1024.0);
    l += g_acc[1] / (24.0 * 256.0 * 512.0);
    l += g_acc[2] / (24.0 * 128.0 * 256.0);
    l += g_acc[3] / (24.0 * 64.0 * 128.0);
    out[0] = (float)l;
}

extern "C" void kernel_launch(void* const* d_in, const int* in_sizes, int n_in,
                              void* d_out, int out_size) {
    const float* depth[4];
    const float* mask[4];
    // Input-order detection: interleaved (dict order) vs grouped (signature order).
    if (in_sizes[2] == 8388608) {
        for (int i = 0; i < 4; i++) {
            depth[i] = (const float*)d_in[1 + 2 * i];
            mask[i]  = (const float*)d_in[2 + 2 * i];
        }
    } else {
        for (int i = 0; i < 4; i++) {
            depth[i] = (const float*)d_in[1 + i];
            mask[i]  = (const float*)d_in[5 + i];
        }
    }
    const float* ref_rgb = (const float*)d_in[0];
    const float* tgt0 = (const float*)d_in[9];
    const float* tgt1 = (const float*)d_in[10];
    const float* pose = (const float*)d_in[11];
    float* out = (float*)d_out;

    bp_init<<<1, 256>>>(pose);
    bp_fused0<<<4096, 256>>>(ref_rgb, tgt0, tgt1, depth[0], mask[0]);
    bp_prep2<<<5120, 256>>>();
    bp_prep3<<<1280, 256>>>();
    bp_loss123<<<5376, 256>>>(depth[1], mask[1], depth[2], mask[2], depth[3], mask[3]);
    bp_finalize<<<1, 1>>>(out);
    (void)n_in; (void)out_size;
}

// round 5
// speedup vs baseline: 1.4874x; 1.0238x over previous
#include <cuda_runtime.h>
#include <math.h>

#define PI_F 3.14159265358979323846f
#define HPI_F 1.57079632679489662f

#define BB 8

// ---------- static scratch ----------
// tgt interleaved mips (B,h,w,3): L1@0 (3145728), L2@3145728 (786432), L3@3932160 (196608)
__device__ __align__(16) float g_tgtM0[4128768];
__device__ __align__(16) float g_tgtM1[4128768];
// ref planar mips ((b*3+c),h,w): same float offsets
__device__ __align__(16) float g_refM[4128768];
__device__ float g_R[BB * 2 * 9];
__device__ float g_t[BB * 2 * 3];
// sincos tables: lon sizes 1024,512,256,128 @ offs 0,1024,1536,1792
//                lat sizes 512,256,128,64  @ offs 0,512,768,896
__device__ float2 g_lonT[1920];
__device__ float2 g_latT[960];
__device__ double g_acc[4];
__device__ int g_done;

// ---------- init ----------
__global__ void bp_init(const float* __restrict__ pose) {
    int tid = threadIdx.x;
    if (tid < 4) g_acc[tid] = 0.0;
    if (tid == 4) g_done = 0;
    if (tid < BB * 2) {
        const float* p = pose + tid * 6;
        float rx = p[3], ry = p[4], rz = p[5];
        float th = sqrtf(rx * rx + ry * ry + rz * rz);
        float inv = 1.0f / fmaxf(th, 1e-8f);
        float kx = rx * inv, ky = ry * inv, kz = rz * inv;
        float s = sinf(th), c = cosf(th), ic = 1.0f - c;
        float* R = g_R + tid * 9;
        R[0] = c + ic * kx * kx;      R[1] = ic * kx * ky - s * kz; R[2] = ic * kx * kz + s * ky;
        R[3] = ic * ky * kx + s * kz; R[4] = c + ic * ky * ky;      R[5] = ic * ky * kz - s * kx;
        R[6] = ic * kz * kx - s * ky; R[7] = ic * kz * ky + s * kx; R[8] = c + ic * kz * kz;
        float* t = g_t + tid * 3;
        t[0] = p[0]; t[1] = p[1]; t[2] = p[2];
    }
    for (int i = tid; i < 1920; i += 256) {
        int off, w;
        if (i < 1024)      { off = 0;    w = 1024; }
        else if (i < 1536) { off = 1024; w = 512; }
        else if (i < 1792) { off = 1536; w = 256; }
        else               { off = 1792; w = 128; }
        int xi = i - off;
        float lon = ((xi + 0.5f) / (float)w * 2.0f - 1.0f) * PI_F;
        g_lonT[i] = make_float2(sinf(lon), cosf(lon));
    }
    for (int i = tid; i < 960; i += 256) {
        int off, h;
        if (i < 512)      { off = 0;   h = 512; }
        else if (i < 768) { off = 512; h = 256; }
        else if (i < 896) { off = 768; h = 128; }
        else              { off = 896; h = 64; }
        int yi = i - off;
        float lat = -((yi + 0.5f) / (float)h * 2.0f - 1.0f) * HPI_F;
        g_latT[i] = make_float2(sinf(lat), cosf(lat));
    }
}

// ---------- fast atan poly on [0,1], max err ~1e-5 rad ----------
__device__ __forceinline__ float atanp(float r) {
    float z = r * r;
    float p = -0.0117212f;
    p = fmaf(p, z, 0.05265332f);
    p = fmaf(p, z, -0.11643287f);
    p = fmaf(p, z, 0.19354346f);
    p = fmaf(p, z, -0.33262347f);
    p = fmaf(p, z, 0.99997726f);
    return r * p;
}

// ---------- one warped-frame L1 term ----------
template <bool PLANAR>
__device__ __forceinline__ float warp_term(
    const float* __restrict__ tg, int b, int h, int w,
    float px, float py, float pz,
    float r0, float r1, float r2, float m)
{
    float ax = fabsf(px), az = fabsf(pz);
    float mn = fminf(ax, az), mx = fmaxf(ax, az);
    float t = atanp(__fdividef(mn, mx));
    t = (ax > az) ? (HPI_F - t) : t;
    t = (pz < 0.0f) ? (PI_F - t) : t;
    float lo = copysignf(t, px);
    float q = py * py;
    float s2 = fmaf(px, px, pz * pz);
    float mn2 = fminf(q, s2), mx2 = fmaxf(q, s2);
    float t2 = atanp(sqrtf(__fdividef(mn2, mx2)));
    t2 = (q > s2) ? (HPI_F - t2) : t2;
    float la = copysignf(t2, py);

    float fx = (lo * (1.0f / PI_F) + 1.0f) * (0.5f * (float)(w - 1));
    float fy = (la * (2.0f / PI_F) + 1.0f) * (0.5f * (float)(h - 1));
    float x0f = floorf(fx), y0f = floorf(fy);
    float wx1 = fx - x0f, wy1 = fy - y0f;
    float wx0 = 1.0f - wx1, wy0 = 1.0f - wy1;
    int x0 = (int)x0f, y0 = (int)y0f;
    int x1 = min(x0 + 1, w - 1), y1 = min(y0 + 1, h - 1);
    x0 = max(min(x0, w - 1), 0); y0 = max(min(y0, h - 1), 0);
    x1 = max(x1, 0); y1 = max(y1, 0);
    float wa = wx0 * wy0, wb = wx0 * wy1, wc = wx1 * wy0, wd = wx1 * wy1;

    float w0, w1, w2;
    if (PLANAR) {
        int hw = h * w;
        const float* base = tg + (size_t)b * 3 * hw;
        int i00 = y0 * w + x0, i01 = y1 * w + x0, i10 = y0 * w + x1, i11 = y1 * w + x1;
        w0 = wa * __ldg(base + i00) + wb * __ldg(base + i01) + wc * __ldg(base + i10) + wd * __ldg(base + i11);
        base += hw;
        w1 = wa * __ldg(base + i00) + wb * __ldg(base + i01) + wc * __ldg(base + i10) + wd * __ldg(base + i11);
        base += hw;
        w2 = wa * __ldg(base + i00) + wb * __ldg(base + i01) + wc * __ldg(base + i10) + wd * __ldg(base + i11);
    } else {
        const float* ra = tg + (size_t)(b * h + y0) * w * 3;
        const float* rb = tg + (size_t)(b * h + y1) * w * 3;
        const float* c00 = ra + x0 * 3; const float* c10 = ra + x1 * 3;
        const float* c01 = rb + x0 * 3; const float* c11 = rb + x1 * 3;
        w0 = wa * __ldg(c00 + 0) + wb * __ldg(c01 + 0) + wc * __ldg(c10 + 0) + wd * __ldg(c11 + 0);
        w1 = wa * __ldg(c00 + 1) + wb * __ldg(c01 + 1) + wc * __ldg(c10 + 1) + wd * __ldg(c11 + 1);
        w2 = wa * __ldg(c00 + 2) + wb * __ldg(c01 + 2) + wc * __ldg(c10 + 2) + wd * __ldg(c11 + 2);
    }
    return m * (fabsf(r0 - w0) + fabsf(r1 - w1) + fabsf(r2 - w2));
}

// ---------- FUSED: loss level 0 + build all L1 mips (1 thread/pixel) ----------
// Block = 16x16 pixel tile. Warp = 16x2 sub-tile (lane = tx + 16*(y&1)).
// 2x2 mip reduction via shfl_xor(1) + shfl_xor(16).
__global__ __launch_bounds__(256) void bp_fused0(
    const float* __restrict__ ref, const float* __restrict__ tgt0,
    const float* __restrict__ tgt1, const float* __restrict__ depth,
    const float* __restrict__ mask)
{
    int tid = threadIdx.x;
    int lane = tid & 31, wid = tid >> 5;
    int blk = blockIdx.x;            // 16384 = 64 x 32 x 8
    int bx = blk & 63;
    int by = (blk >> 6) & 31;
    int b  = blk >> 11;
    int tx = lane & 15;
    int sub = lane >> 4;
    int x = bx * 16 + tx;
    int y = by * 16 + wid * 2 + sub;

    const int hw = 512 * 1024;
    int p = y * 1024 + x;
    size_t base3 = (size_t)b * 3 * hw + p;

    float r0 = __ldg(ref + base3), r1 = __ldg(ref + base3 + hw), r2 = __ldg(ref + base3 + 2 * hw);
    float t00 = __ldg(tgt0 + base3), t01 = __ldg(tgt0 + base3 + hw), t02 = __ldg(tgt0 + base3 + 2 * hw);
    float t10 = __ldg(tgt1 + base3), t11 = __ldg(tgt1 + base3 + hw), t12 = __ldg(tgt1 + base3 + 2 * hw);
    float d  = __ldg(depth + (size_t)b * hw + p);
    float m0 = __ldg(mask + (size_t)(b * 2) * hw + p);
    float m1 = __ldg(mask + (size_t)(b * 2 + 1) * hw + p);

    // ---- mip reduction (2x2) via shuffles ----
    #define RED4(v) { v += __shfl_xor_sync(0xffffffffu, v, 1); v += __shfl_xor_sync(0xffffffffu, v, 16); v *= 0.25f; }
    float a0 = r0, a1 = r1, a2 = r2;
    float c00 = t00, c01 = t01, c02 = t02;
    float c10 = t10, c11 = t11, c12 = t12;
    RED4(a0); RED4(a1); RED4(a2);
    RED4(c00); RED4(c01); RED4(c02);
    RED4(c10); RED4(c11); RED4(c12);
    if (sub == 0 && (tx & 1) == 0) {
        int x2 = x >> 1, y2 = y >> 1;
        size_t ro = (size_t)b * 393216 + y2 * 512 + x2;
        g_refM[ro] = a0; g_refM[ro + 131072] = a1; g_refM[ro + 262144] = a2;
        float* o0 = g_tgtM0 + (size_t)((b * 256 + y2) * 512 + x2) * 3;
        o0[0] = c00; o0[1] = c01; o0[2] = c02;
        float* o1 = g_tgtM1 + (size_t)((b * 256 + y2) * 512 + x2) * 3;
        o1[0] = c10; o1[1] = c11; o1[2] = c12;
    }
    #undef RED4

    // ---- loss ----
    float2 lc = g_lonT[x];
    float2 lt = g_latT[y];
    float xx = d * lt.y * lc.x;
    float yy = d * lt.x;
    float zz = d * lt.y * lc.y;
    float acc = 0.0f;
    #pragma unroll
    for (int n = 0; n < 2; n++) {
        const float* Rm = g_R + (b * 2 + n) * 9;
        const float* tv = g_t + (b * 2 + n) * 3;
        float px = __ldg(Rm+0) * xx + __ldg(Rm+1) * yy + __ldg(Rm+2) * zz + __ldg(tv+0);
        float py = __ldg(Rm+3) * xx + __ldg(Rm+4) * yy + __ldg(Rm+5) * zz + __ldg(tv+1);
        float pz = __ldg(Rm+6) * xx + __ldg(Rm+7) * yy + __ldg(Rm+8) * zz + __ldg(tv+2);
        acc += warp_term<true>(n ? tgt1 : tgt0, b, 512, 1024, px, py, pz, r0, r1, r2, n ? m1 : m0);
    }
    // block reduce -> g_acc[0]
    #pragma unroll
    for (int o = 16; o > 0; o >>= 1) acc += __shfl_down_sync(0xffffffffu, acc, o);
    __shared__ float ws[8];
    if (lane == 0) ws[wid] = acc;
    __syncthreads();
    if (tid == 0) {
        float s = 0.0f;
        #pragma unroll
        for (int i = 0; i < 8; i++) s += ws[i];
        atomicAdd(&g_acc[0], (double)s);
    }
}

// ---------- FUSED prep: L1 -> L2 + L3 (thread owns 4x4 L1 block) ----------
__global__ __launch_bounds__(256) void bp_prep23() {
    int blk = blockIdx.x, tid = threadIdx.x;
    if (blk < 512) {
        float* M = (blk < 256) ? g_tgtM0 : g_tgtM1;
        int idx = (blk & 255) * 256 + tid;           // [0, 65536) = one L3 pixel
        int x3 = idx & 127, y3 = (idx >> 7) & 63, b = idx >> 13;
        int x1 = x3 * 4, y1 = y3 * 4;
        float v[4][12];
        #pragma unroll
        for (int r = 0; r < 4; r++) {
            const float4* s = (const float4*)(M + (size_t)((b * 256 + y1 + r) * 512 + x1) * 3);
            float4 q0 = s[0], q1 = s[1], q2 = s[2];
            v[r][0] = q0.x; v[r][1] = q0.y; v[r][2] = q0.z; v[r][3] = q0.w;
            v[r][4] = q1.x; v[r][5] = q1.y; v[r][6] = q1.z; v[r][7] = q1.w;
            v[r][8] = q2.x; v[r][9] = q2.y; v[r][10] = q2.z; v[r][11] = q2.w;
        }
        float l3[3] = {0.f, 0.f, 0.f};
        #pragma unroll
        for (int j = 0; j < 2; j++) {
            #pragma unroll
            for (int i = 0; i < 2; i++) {
                float* o = M + 3145728 + (size_t)((b * 128 + 2 * y3 + j) * 256 + 2 * x3 + i) * 3;
                #pragma unroll
                for (int c = 0; c < 3; c++) {
                    float s4 = 0.25f * (v[2*j][(2*i)*3 + c] + v[2*j][(2*i+1)*3 + c]
                                      + v[2*j+1][(2*i)*3 + c] + v[2*j+1][(2*i+1)*3 + c]);
                    o[c] = s4;
                    l3[c] += 0.25f * s4;
                }
            }
        }
        float* o3 = M + 3932160 + (size_t)((b * 64 + y3) * 128 + x3) * 3;
        o3[0] = l3[0]; o3[1] = l3[1]; o3[2] = l3[2];
    } else {
        int j = (blk - 512) * 256 + tid;             // [0, 196608) = one ref L3 element
        int x3 = j & 127, y3 = (j >> 7) & 63, pp = j >> 13;   // pp = b*3+c
        int x1 = x3 * 4, y1 = y3 * 4;
        float4 q[4];
        #pragma unroll
        for (int r = 0; r < 4; r++)
            q[r] = *(const float4*)(g_refM + (size_t)pp * 131072 + (y1 + r) * 512 + x1);
        float s00 = 0.25f * (q[0].x + q[0].y + q[1].x + q[1].y);
        float s01 = 0.25f * (q[0].z + q[0].w + q[1].z + q[1].w);
        float s10 = 0.25f * (q[2].x + q[2].y + q[3].x + q[3].y);
        float s11 = 0.25f * (q[2].z + q[2].w + q[3].z + q[3].w);
        size_t l2b = 3145728 + (size_t)(pp * 128 + 2 * y3) * 256 + 2 * x3;
        g_refM[l2b] = s00; g_refM[l2b + 1] = s01;
        g_refM[l2b + 256] = s10; g_refM[l2b + 257] = s11;
        g_refM[3932160 + (size_t)(pp * 64 + y3) * 128 + x3] = 0.25f * (s00 + s01 + s10 + s11);
    }
}

// ---------- loss levels 1..3 merged + finalize ----------
__global__ __launch_bounds__(256) void bp_loss123(
    const float* __restrict__ d1, const float* __restrict__ m1,
    const float* __restrict__ d2, const float* __restrict__ m2,
    const float* __restrict__ d3, const float* __restrict__ m3,
    float* __restrict__ out)
{
    int blk = blockIdx.x;
    const float *dep, *msk;
    int h, w, lw, lh, lonO, latO, accI, base;
    size_t toff;
    if (blk < 4096)      { dep = d1; msk = m1; h = 256; w = 512; lw = 9; lh = 8; lonO = 1024; latO = 512; toff = 0;       accI = 1; base = 0; }
    else if (blk < 5120) { dep = d2; msk = m2; h = 128; w = 256; lw = 8; lh = 7; lonO = 1536; latO = 768; toff = 3145728; accI = 2; base = 4096; }
    else                 { dep = d3; msk = m3; h = 64;  w = 128; lw = 7; lh = 6; lonO = 1792; latO = 896; toff = 3932160; accI = 3; base = 5120; }
    int idx = (blk - base) * 256 + threadIdx.x;
    int x = idx & (w - 1), y = (idx >> lw) & (h - 1), b = idx >> (lw + lh);
    float2 lc = g_lonT[lonO + x];
    float2 lt = g_latT[latO + y];
    float d = __ldg(dep + idx);
    float xx = d * lt.y * lc.x;
    float yy = d * lt.x;
    float zz = d * lt.y * lc.y;
    int hw = h * w;
    int p = y * w + x;
    const float* rp = g_refM + toff + (size_t)b * 3 * hw + p;
    float r0 = rp[0], r1 = rp[hw], r2 = rp[2 * hw];
    const float* tg0 = g_tgtM0 + toff;
    const float* tg1 = g_tgtM1 + toff;
    float acc = 0.0f;
    #pragma unroll
    for (int n = 0; n < 2; n++) {
        const float* Rm = g_R + (b * 2 + n) * 9;
        const float* tv = g_t + (b * 2 + n) * 3;
        float px = __ldg(Rm+0) * xx + __ldg(Rm+1) * yy + __ldg(Rm+2) * zz + __ldg(tv+0);
        float py = __ldg(Rm+3) * xx + __ldg(Rm+4) * yy + __ldg(Rm+5) * zz + __ldg(tv+1);
        float pz = __ldg(Rm+6) * xx + __ldg(Rm+7) * yy + __ldg(Rm+8) * zz + __ldg(tv+2);
        float m = __ldg(msk + (size_t)(b * 2 + n) * hw + p);
        acc += warp_term<false>(n ? tg1 : tg0, b, h, w, px, py, pz, r0, r1, r2, m);
    }
    // block reduce + atomic + last-block finalize
    #pragma unroll
    for (int o = 16; o > 0; o >>= 1) acc += __shfl_down_sync(0xffffffffu, acc, o);
    __shared__ float ws[8];
    int lane = threadIdx.x & 31, warp = threadIdx.x >> 5;
    if (lane == 0) ws[warp] = acc;
    __syncthreads();
    if (threadIdx.x == 0) {
        float s = 0.0f;
        #pragma unroll
        for (int i = 0; i < 8; i++) s += ws[i];
        atomicAdd(&g_acc[accI], (double)s);
        __threadfence();
        int done = atomicAdd(&g_done, 1);
        if (done == 5375) {
            double l = g_acc[0] * (1.0 / 12582912.0)
                     + g_acc[1] * (1.0 / 3145728.0)
                     + g_acc[2] * (1.0 / 786432.0)
                     + g_acc[3] * (1.0 / 196608.0);
            out[0] = (float)l;
        }
    }
}

extern "C" void kernel_launch(void* const* d_in, const int* in_sizes, int n_in,
                              void* d_out, int out_size) {
    const float* depth[4];
    const float* mask[4];
    // Input-order detection: interleaved (dict order) vs grouped (signature order).
    if (in_sizes[2] == 8388608) {
        for (int i = 0; i < 4; i++) {
            depth[i] = (const float*)d_in[1 + 2 * i];
            mask[i]  = (const float*)d_in[2 + 2 * i];
        }
    } else {
        for (int i = 0; i < 4; i++) {
            depth[i] = (const float*)d_in[1 + i];
            mask[i]  = (const float*)d_in[5 + i];
        }
    }
    const float* ref_rgb = (const float*)d_in[0];
    const float* tgt0 = (const float*)d_in[9];
    const float* tgt1 = (const float*)d_in[10];
    const float* pose = (const float*)d_in[11];
    float* out = (float*)d_out;

    bp_init<<<1, 256>>>(pose);
    bp_fused0<<<16384, 256>>>(ref_rgb, tgt0, tgt1, depth[0], mask[0]);
    bp_prep23<<<1280, 256>>>();
    bp_loss123<<<5376, 256>>>(depth[1], mask[1], depth[2], mask[2], depth[3], mask[3], out);
    (void)n_in; (void)out_size;
}